// round 8
// baseline (speedup 1.0000x reference)
#include <cuda_runtime.h>
#include <cstring>

// DTree_84061099917446 — soft decision tree forward pass.
// N=262144 rows, F=32, depth 8, 255 nodes, 256 leaves, C=1.
//
// R8: tcgen05 is unavailable (harness compiles via compute_100, not 100a),
// so optimize the SIMT kernel's real bottleneck: L1 return bandwidth for the
// per-node W reads (86.7% L1 in R6). Split W across TWO load ports:
//   features 0..7  -> __constant__ bank (literal offsets, LDC/LDCU port)
//   features 8..31 -> shared memory (6x LDS.128/node)
// With ~20 cyc smem + ~4-16 cyc const vs ~21 cyc fma per node, the fma pipe
// becomes binding. Fully unrolled tree (literal node indices), W pre-scaled
// by -log2(e), gate = EX2+FADD+RCP, depth-7 leaf-pair folding, 1 row/thread
// at 64-reg budget -> 32 warps/SM.

#define F_      32
#define NODES_  255
#define N_ROWS  262144
#define TPB     256
#define LOG2E_F 1.4426950408889634f

typedef unsigned long long u64;
typedef unsigned int u32;

// Constant-bank slice of W': features 0..7 of each node (2x ulonglong2).
__constant__ ulonglong2 cW[NODES_ * 2];                  // 8160 B

// Device-global staging / smem sources (scratch; no allocation).
__device__ __align__(16) ulonglong2 g_cstage[NODES_ * 2]; // -> cW via memcpy
__device__ __align__(16) float g_Wsm[NODES_ * 24];        // features 8..31
__device__ u64    g_b2[NODES_];                           // packed (+log2e*c, 0)
__device__ float2 g_pr[128];                              // (clsR, clsL-clsR)

// ---------------------------------------------------------------------------
__device__ __forceinline__ u64 pk2(float lo, float hi) {
    u64 r;
    asm("mov.b64 %0, {%1, %2};" : "=l"(r) : "f"(lo), "f"(hi));
    return r;
}

// ---------------------------------------------------------------------------
// Prologue: one block, 256 threads. Thread t<255 handles node t (serial over
// 32 features — trivial cost). Threads t<128 also build the leaf-pair table.
// ---------------------------------------------------------------------------
__global__ void prep_kernel(const float* __restrict__ fi,
                            const float* __restrict__ fs,
                            const float* __restrict__ cls) {
    int t = threadIdx.x;
    if (t < NODES_) {
        float bias = 0.0f;
        float wp[F_];
        #pragma unroll
        for (int f = 0; f < F_; ++f) {
            int idx = t * F_ + f;
            float w = fmaxf(fi[idx], 0.0f);
            float s = 1.0f / (1.0f + expf(-fs[idx]));
            bias += w * s;
            wp[f] = -LOG2E_F * w;
        }
        // features 0..7 -> constant staging (pairs packed)
        ulonglong2 c0, c1;
        c0.x = pk2(wp[0], wp[1]); c0.y = pk2(wp[2], wp[3]);
        c1.x = pk2(wp[4], wp[5]); c1.y = pk2(wp[6], wp[7]);
        g_cstage[t * 2]     = c0;
        g_cstage[t * 2 + 1] = c1;
        // features 8..31 -> smem source
        #pragma unroll
        for (int f = 8; f < F_; ++f) g_Wsm[t * 24 + (f - 8)] = wp[f];
        g_b2[t] = pk2(LOG2E_F * bias, 0.0f);
    }
    if (t < 128) {
        float lv = cls[2 * t];
        float rv = cls[2 * t + 1];
        g_pr[t] = make_float2(rv, lv - rv);
    }
}

// ---------------------------------------------------------------------------
// Packed f32x2 / gate helpers.
// ---------------------------------------------------------------------------
__device__ __forceinline__ u64 ffma2(u64 a, u64 b, u64 c) {
    u64 d;
    asm("fma.rn.f32x2 %0, %1, %2, %3;" : "=l"(d) : "l"(a), "l"(b), "l"(c));
    return d;
}

__device__ __forceinline__ float psum(u64 a, u64 b) {
    u64 s;
    asm("add.rn.f32x2 %0, %1, %2;" : "=l"(s) : "l"(a), "l"(b));
    float lo, hi;
    asm("mov.b64 {%0, %1}, %2;" : "=f"(lo), "=f"(hi) : "l"(s));
    return lo + hi;
}

// y = -log2e * z  ->  g = sigmoid(z) = 1 / (1 + 2^y)
__device__ __forceinline__ float fgate(float y) {
    float e, g;
    asm("ex2.approx.f32 %0, %1;" : "=f"(e) : "f"(y));
    float d = 1.0f + e;
    asm("rcp.approx.f32 %0, %1;" : "=f"(g) : "f"(d));
    return g;
}

// ---------------------------------------------------------------------------
// Compile-time-unrolled DFS. NODE literal everywhere: const-bank reads get
// immediate offsets; smem reads get immediate offsets. Depth-7 nodes fold
// their two leaves: acc += prod * (clsR + g*(clsL - clsR)).
// ---------------------------------------------------------------------------
template<int DEPTH, int NODE>
__device__ __forceinline__ void subtree(const float*  __restrict__ sW,
                                        const u64*    __restrict__ sb2,
                                        const float2* __restrict__ sp,
                                        const u64 (&xa)[16],
                                        float prod, float& acc) {
    u64 A0 = sb2[NODE];                // init = (+log2e*c, 0)
    u64 A1 = 0ull;
    // const-bank part: features 0..7 (xa[0..3])
    {
        ulonglong2 w0 = cW[NODE * 2];
        ulonglong2 w1 = cW[NODE * 2 + 1];
        A0 = ffma2(xa[0], w0.x, A0);
        A1 = ffma2(xa[1], w0.y, A1);
        A0 = ffma2(xa[2], w1.x, A0);
        A1 = ffma2(xa[3], w1.y, A1);
    }
    // smem part: features 8..31 (xa[4..15]); NODE*96 B is 16B-aligned
    {
        const ulonglong2* wp =
            reinterpret_cast<const ulonglong2*>(sW + NODE * 24);
        #pragma unroll
        for (int i = 0; i < 6; ++i) {
            ulonglong2 w = wp[i];
            A0 = ffma2(xa[4 + 2 * i], w.x, A0);
            A1 = ffma2(xa[5 + 2 * i], w.y, A1);
        }
    }
    float g = fgate(psum(A0, A1));

    if constexpr (DEPTH == 7) {
        float2 pr = sp[NODE - 127];               // (clsR, clsL - clsR)
        acc = fmaf(prod, fmaf(g, pr.y, pr.x), acc);
    } else {
        float r = fmaf(-prod, g, prod);           // prod*(1-g)
        subtree<DEPTH + 1, 2 * NODE + 1>(sW, sb2, sp, xa, prod * g, acc);
        subtree<DEPTH + 1, 2 * NODE + 2>(sW, sb2, sp, xa, r, acc);
    }
}

// ---------------------------------------------------------------------------
__global__ void __launch_bounds__(TPB, 4)
dtree_kernel(const float* __restrict__ x,
             float* __restrict__ out) {
    __shared__ __align__(16) float sW[NODES_ * 24];   // 24480 B
    __shared__ u64    sb2[NODES_];                    //  2040 B
    __shared__ float2 sp[128];                        //  1024 B

    for (int i = threadIdx.x; i < NODES_ * 24; i += TPB) sW[i] = g_Wsm[i];
    if (threadIdx.x < NODES_) sb2[threadIdx.x] = g_b2[threadIdx.x];
    if (threadIdx.x < 128)    sp[threadIdx.x]  = g_pr[threadIdx.x];
    __syncthreads();

    int row = blockIdx.x * TPB + threadIdx.x;

    // Row features as 16 packed f32x2 (feature pairs), 2x LDG.128.
    u64 xa[16];
    {
        const ulonglong2* pa =
            reinterpret_cast<const ulonglong2*>(x + (size_t)row * F_);
        #pragma unroll
        for (int i = 0; i < 8; ++i) {
            ulonglong2 v = pa[i];
            xa[2 * i] = v.x; xa[2 * i + 1] = v.y;
        }
    }

    float acc = 0.0f;
    subtree<0, 0>(sW, sb2, sp, xa, 1.0f, acc);

    out[row] = acc;
}

// ---------------------------------------------------------------------------
extern "C" void kernel_launch(void* const* d_in, const int* in_sizes, int n_in,
                              void* d_out, int out_size) {
    const float* x   = (const float*)d_in[0];   // (N, 32)
    const float* fi  = (const float*)d_in[1];   // (255*32, 1)
    const float* fs  = (const float*)d_in[2];   // (255*32, 1)
    const float* cls = (const float*)d_in[3];   // (256, 1)
    float* out = (float*)d_out;                 // (N, 1) float32

    prep_kernel<<<1, 256>>>(fi, fs, cls);

    // Publish the const-bank slice (async D2D -> graph-capturable, no alloc).
    void* src = nullptr;
    cudaGetSymbolAddress(&src, g_cstage);
    cudaMemcpyToSymbolAsync(cW, src, sizeof(ulonglong2) * NODES_ * 2, 0,
                            cudaMemcpyDeviceToDevice, 0);

    dtree_kernel<<<N_ROWS / TPB, TPB>>>(x, out);
}